// round 1
// baseline (speedup 1.0000x reference)
#include <cuda_runtime.h>
#include <math_constants.h>

// ---------------- problem constants ----------------
#define BATCH 4
#define HW    16384          // 128*128
#define THR   0.1f
#define TS    1024           // shared column tile
#define RPT   8              // rows per thread in dist kernel
#define DBLK  128            // threads per dist block  -> 1024 rows/block
#define COLCHUNK 2048        // columns per block (grid.y = 8)

// ---------------- device scratch (no allocs allowed) ----------------
__device__ float g_px[2][BATCH][HW];
__device__ float g_py[2][BATCH][HW];
__device__ float g_pn[2][BATCH][HW];
__device__ int   g_cnt[2][BATCH];
__device__ unsigned int g_minbuf[8][HW];   // [dir*4+b][row], orderable-uint encoded
__device__ float g_sum[8];

// ---------------- helpers ----------------
__device__ __forceinline__ unsigned fp_ord(float f) {
    unsigned u = __float_as_uint(f);
    return (u & 0x80000000u) ? ~u : (u | 0x80000000u);
}
__device__ __forceinline__ float fp_unord(unsigned u) {
    u = (u & 0x80000000u) ? (u & 0x7fffffffu) : ~u;
    return __uint_as_float(u);
}
__device__ __forceinline__ unsigned long long pack2(float lo, float hi) {
    unsigned long long r;
    asm("mov.b64 %0, {%1,%2};" : "=l"(r) : "f"(lo), "f"(hi));
    return r;
}
__device__ __forceinline__ void unpack2(unsigned long long p, float& lo, float& hi) {
    asm("mov.b64 {%0,%1}, %2;" : "=f"(lo), "=f"(hi) : "l"(p));
}
__device__ __forceinline__ unsigned long long fma2(unsigned long long a,
                                                   unsigned long long b,
                                                   unsigned long long c) {
    unsigned long long d;
    asm("fma.rn.f32x2 %0, %1, %2, %3;" : "=l"(d) : "l"(a), "l"(b), "l"(c));
    return d;
}

// ---------------- kernel 0: zero counters ----------------
__global__ void k_zero() {
    if (threadIdx.x < 8) ((int*)g_cnt)[threadIdx.x] = 0;
}

// ---------------- kernel 1: compaction + minbuf init ----------------
// grid 8 blocks (set*4+b), 256 threads
__global__ void k_compact(const float* __restrict__ b1, const float* __restrict__ b2) {
    int bs = blockIdx.x;
    int set = bs >> 2, b = bs & 3;
    const float* src = (set == 0 ? b1 : b2) + b * HW;

    // init min buffer slice (dir == set for row ownership)
    for (int i = threadIdx.x; i < HW; i += 256) g_minbuf[bs][i] = 0xFFFFFFFFu;

    int lane = threadIdx.x & 31;
    for (int i = threadIdx.x; i < HW; i += 256) {   // uniform trip count: ballot safe
        float v = src[i];
        float w = v - THR;
        bool act = (w > 0.0f);
        unsigned mask = __ballot_sync(0xffffffffu, act);
        int c = __popc(mask);
        int base = 0;
        if (lane == 0 && c) base = atomicAdd(&g_cnt[set][b], c);
        base = __shfl_sync(0xffffffffu, base, 0);
        if (act) {
            int pos = base + __popc(mask & ((1u << lane) - 1u));
            float y = (float)(i >> 7);
            float x = (float)(i & 127);
            float px = y * w, py = x * w;
            g_px[set][b][pos] = px;
            g_py[set][b][pos] = py;
            g_pn[set][b][pos] = fmaf(px, px, py * py);
        }
    }
}

// ---------------- kernel 2: pairwise min (GEMM-form) ----------------
// grid (16, 8, 8): x=row chunk (1024 rows), y=col chunk (2048 cols), z=dir*4+b
__global__ void __launch_bounds__(DBLK) k_dist() {
    int z = blockIdx.z;
    int dir = z >> 2, b = z & 3;
    int n1 = g_cnt[dir][b];          // rows come from set==dir
    int n2 = g_cnt[dir ^ 1][b];      // columns from the other set

    int rowBase = blockIdx.x * (DBLK * RPT);
    int colBase = blockIdx.y * COLCHUNK;
    if (rowBase >= n1 || colBase >= n2) return;   // uniform per block
    int colEnd = min(colBase + COLCHUNK, n2);

    __shared__ __align__(16) float sqx[TS];
    __shared__ __align__(16) float sqy[TS];
    __shared__ __align__(16) float sqn[TS];

    const float* qx = g_px[dir ^ 1][b];
    const float* qy = g_py[dir ^ 1][b];
    const float* qn = g_pn[dir ^ 1][b];

    int t = threadIdx.x;

    unsigned long long a2[RPT], b2[RPT];
    float mn[RPT];
#pragma unroll
    for (int r = 0; r < RPT; r++) {
        int row = rowBase + t + r * DBLK;
        float px = 0.0f, py = 0.0f;
        if (row < n1) { px = g_px[dir][b][row]; py = g_py[dir][b][row]; }
        float a = -2.0f * px, bb = -2.0f * py;
        a2[r] = pack2(a, a);
        b2[r] = pack2(bb, bb);
        mn[r] = CUDART_INF_F;
    }

    const float FINF = CUDART_INF_F;
    for (int tb = colBase; tb < colEnd; tb += TS) {
        int cnt = colEnd - tb;            // >= 1
        __syncthreads();
        for (int j = t; j < TS; j += DBLK) {
            if (j < cnt) { sqx[j] = qx[tb + j]; sqy[j] = qy[tb + j]; sqn[j] = qn[tb + j]; }
            else         { sqx[j] = 0.0f;       sqy[j] = 0.0f;       sqn[j] = FINF;       }
        }
        __syncthreads();

#pragma unroll 4
        for (int j = 0; j < TS; j += 2) {
            unsigned long long qx2 = *(const unsigned long long*)&sqx[j];
            unsigned long long qy2 = *(const unsigned long long*)&sqy[j];
            unsigned long long qn2 = *(const unsigned long long*)&sqn[j];
#pragma unroll
            for (int r = 0; r < RPT; r++) {
                unsigned long long tp = fma2(b2[r], qy2, qn2);
                unsigned long long vp = fma2(a2[r], qx2, tp);
                float lo, hi;
                unpack2(vp, lo, hi);
                mn[r] = fminf(mn[r], lo);
                mn[r] = fminf(mn[r], hi);
            }
        }
    }

#pragma unroll
    for (int r = 0; r < RPT; r++) {
        int row = rowBase + t + r * DBLK;
        if (row < n1) atomicMin(&g_minbuf[z][row], fp_ord(mn[r]));
    }
}

// ---------------- kernel 3: per-direction sums ----------------
// grid 8 blocks, 256 threads
__global__ void k_final() {
    int z = blockIdx.x;
    int dir = z >> 2, b = z & 3;
    int n1 = g_cnt[dir][b];
    const float* pn = g_pn[dir][b];

    float s = 0.0f;
    for (int i = threadIdx.x; i < n1; i += 256) {
        float mv = fp_unord(g_minbuf[z][i]);
        float d2 = pn[i] + mv;
        s += sqrtf(fmaxf(d2, 1e-12f));
    }
    // reduce 256 -> 1
    for (int o = 16; o; o >>= 1) s += __shfl_down_sync(0xffffffffu, s, o);
    __shared__ float ws[8];
    if ((threadIdx.x & 31) == 0) ws[threadIdx.x >> 5] = s;
    __syncthreads();
    if (threadIdx.x < 8) {
        float v = ws[threadIdx.x];
        for (int o = 4; o; o >>= 1) v += __shfl_down_sync(0xffu, v, o);
        if (threadIdx.x == 0) g_sum[z] = v / (float)max(n1, 1);
    }
}

// ---------------- kernel 4: combine + empty sentinel ----------------
__global__ void k_out(float* __restrict__ out) {
    int b = threadIdx.x;
    if (b < BATCH) {
        int n1 = g_cnt[0][b], n2 = g_cnt[1][b];
        out[b] = (n1 > 0 && n2 > 0) ? (g_sum[b] + g_sum[4 + b]) : 1.0e6f;
    }
}

// ---------------- launch ----------------
extern "C" void kernel_launch(void* const* d_in, const int* in_sizes, int n_in,
                              void* d_out, int out_size) {
    const float* b1 = (const float*)d_in[0];
    const float* b2 = (const float*)d_in[1];
    float* out = (float*)d_out;

    k_zero<<<1, 32>>>();
    k_compact<<<8, 256>>>(b1, b2);
    dim3 grid(HW / (DBLK * RPT), HW / COLCHUNK, 8);   // (16, 8, 8)
    k_dist<<<grid, DBLK>>>();
    k_final<<<8, 256>>>();
    k_out<<<1, 32>>>(out);
}